// round 6
// baseline (speedup 1.0000x reference)
#include <cuda_runtime.h>
#include <cuda_fp16.h>
#include <math.h>
#include <stdint.h>

#define TOKENS 65536
#define DIN 512
#define HDIM 256
#define BM 64             // tokens per CTA tile
#define KC 64             // fp32 K elements per chunk
#define NCHUNK 8          // 512/64
#define NT 256            // threads per CTA
#define ROWB 144          // padded smem row bytes (64 fp16 = 128B + 16B pad)
#define GRID 304          // 2 CTAs/SM x 152 SMs, persistent

// ---- dynamic SMEM layout (bytes) ----
#define A_OFF     0       // 2 stages x 9216 (64 rows * 144)
#define A_STAGE   9216
#define B_OFF     18432   // 2 stages x 36864 (256 rows * 144)
#define B_STAGE   36864
#define TOK_OFF   92160   // int[64]
#define W2_OFF    92416   // float[6*256]
#define B1_OFF    98560   // float[256]
#define B2_OFF    99584   // float[8]
#define RED_OFF   99616   // float[4][64][6]
#define TILE_OFF  105760  // int
#define SMEM_TOTAL 105792

// ---------------- device globals (allocation-free scratch) ----------------
__device__ int g_vcount, g_pcount, g_ticket;
__device__ int g_vidx[TOKENS];
__device__ int g_pidx[TOKENS];
// prepacked W1 fp16, both heads: [head][chunk 8][256 rows x 128B]
__device__ __align__(16) unsigned char g_wpack[2 * NCHUNK * 32768];

// ---------------- PTX helpers ----------------
__device__ __forceinline__ uint32_t smem_u32(const void* p) {
    uint32_t a;
    asm("{ .reg .u64 t; cvta.to.shared.u64 t, %1; cvt.u32.u64 %0, t; }" : "=r"(a) : "l"(p));
    return a;
}
__device__ __forceinline__ void cp_async16(uint32_t dst, const void* src) {
    asm volatile("cp.async.ca.shared.global [%0], [%1], 16;" :: "r"(dst), "l"(src) : "memory");
}
#define CP_COMMIT() asm volatile("cp.async.commit_group;" ::: "memory")
#define CP_WAIT0()  asm volatile("cp.async.wait_group 0;" ::: "memory")

__device__ __forceinline__ void ldm4(uint32_t (&r)[4], uint32_t addr) {
    asm volatile("ldmatrix.sync.aligned.m8n8.x4.shared.b16 {%0,%1,%2,%3}, [%4];"
        : "=r"(r[0]), "=r"(r[1]), "=r"(r[2]), "=r"(r[3]) : "r"(addr));
}
__device__ __forceinline__ void mma16816(float (&d)[4], const uint32_t (&a)[4],
                                         uint32_t b0, uint32_t b1) {
    asm volatile(
        "mma.sync.aligned.m16n8k16.row.col.f32.f16.f16.f32 "
        "{%0,%1,%2,%3},{%4,%5,%6,%7},{%8,%9},{%0,%1,%2,%3};"
        : "+f"(d[0]), "+f"(d[1]), "+f"(d[2]), "+f"(d[3])
        : "r"(a[0]), "r"(a[1]), "r"(a[2]), "r"(a[3]), "r"(b0), "r"(b1));
}

// ---------------- kernel: prepack W1 fp16 + reset counters ----------------
__global__ void pack_kernel(const float* __restrict__ vW1, const float* __restrict__ pW1) {
    if (blockIdx.x == 0 && blockIdx.y == 0 && threadIdx.x == 0) {
        g_vcount = 0; g_pcount = 0; g_ticket = 0;
    }
    int head = blockIdx.y;
    const float* W = head ? pW1 : vW1;
    int q  = blockIdx.x * blockDim.x + threadIdx.x;  // 0..32767
    int n  = q >> 7;                                 // H row 0..255
    int kq = (q & 127) * 4;                          // k 0..508
    float4 f = *(const float4*)(W + (size_t)n * DIN + kq);

    uint16_t h0 = __half_as_ushort(__float2half_rn(f.x));
    uint16_t h1 = __half_as_ushort(__float2half_rn(f.y));
    uint16_t h2 = __half_as_ushort(__float2half_rn(f.z));
    uint16_t h3 = __half_as_ushort(__float2half_rn(f.w));
    uint2 hv;
    hv.x = (uint32_t)h0 | ((uint32_t)h1 << 16);
    hv.y = (uint32_t)h2 | ((uint32_t)h3 << 16);

    int chunk = kq >> 6;           // KC=64
    int kk = kq & 63;
    unsigned char* basep = g_wpack + (size_t)head * (NCHUNK * 32768) + (size_t)chunk * 32768;
    *(uint2*)(basep + (size_t)n * 128 + kk * 2) = hv;
}

// ---------------- kernel: classify + zero output + masks ----------------
__global__ void classify_kernel(const int* __restrict__ ids32,
                                float* __restrict__ out, int mask_mode) {
    __shared__ int sIs64;
    if (threadIdx.x < 32) {
        int v = ids32[2 * threadIdx.x + 1] | ids32[2 * threadIdx.x + 65] |
                ids32[2 * threadIdx.x + 129] | ids32[2 * threadIdx.x + 193];
        unsigned nz = __ballot_sync(0xffffffffu, v != 0);
        if (threadIdx.x == 0) sIs64 = (nz == 0);
    }
    __syncthreads();
    int t = blockIdx.x * blockDim.x + threadIdx.x;
    if (t >= TOKENS) return;
    int type = sIs64 ? ids32[2 * t] : ids32[t];
    bool vm = (type == 1);
    bool pm = (type == 2);

    float* row = out + (size_t)t * 6;
    #pragma unroll
    for (int o = 0; o < 6; o++) row[o] = 0.0f;

    if (mask_mode == 1) {
        out[TOKENS * 6 + t]          = vm ? 1.0f : 0.0f;
        out[TOKENS * 6 + TOKENS + t] = pm ? 1.0f : 0.0f;
    } else if (mask_mode == 2) {
        unsigned char* m = (unsigned char*)(out + TOKENS * 6);
        m[t]          = vm ? 1 : 0;
        m[TOKENS + t] = pm ? 1 : 0;
    }

    int lane = threadIdx.x & 31;
    unsigned vb = __ballot_sync(0xffffffffu, vm);
    if (vm) {
        int leader = __ffs(vb) - 1;
        int base = 0;
        if (lane == leader) base = atomicAdd(&g_vcount, __popc(vb));
        base = __shfl_sync(vb, base, leader);
        g_vidx[base + __popc(vb & ((1u << lane) - 1u))] = t;
    }
    unsigned pb = __ballot_sync(0xffffffffu, pm);
    if (pm) {
        int leader = __ffs(pb) - 1;
        int base = 0;
        if (lane == leader) base = atomicAdd(&g_pcount, __popc(pb));
        base = __shfl_sync(pb, base, leader);
        g_pidx[base + __popc(pb & ((1u << lane) - 1u))] = t;
    }
}

// ---------------- kernel: persistent fp16 HMMA MLP (KC=64) ----------------
__global__ __launch_bounds__(NT, 2)
void mlp_kernel(const float* __restrict__ repr3,
                const float* __restrict__ vW2, const float* __restrict__ vB1, const float* __restrict__ vB2,
                const float* __restrict__ pW2, const float* __restrict__ pB1, const float* __restrict__ pB2,
                float* __restrict__ out)
{
    extern __shared__ unsigned char smem[];
    const uint32_t sb = smem_u32(smem);
    const int tid  = threadIdx.x;
    const int wid  = tid >> 5;
    const int lane = tid & 31;
    const int wm = wid & 1;          // 2 M tiles of 32 rows
    const int wn = wid >> 1;         // 4 N tiles of 64 cols
    const int m0 = wm * 32;
    const int n0 = wn * 64;

    int*   sTok  = (int*)(smem + TOK_OFF);
    float* sW2   = (float*)(smem + W2_OFF);
    float* sB1   = (float*)(smem + B1_OFF);
    float* sB2   = (float*)(smem + B2_OFF);
    float* sRed  = (float*)(smem + RED_OFF);
    int*   sTile = (int*)(smem + TILE_OFF);

    const int nv = g_vcount, np = g_pcount;
    const int nvt = (nv + BM - 1) / BM;
    const int npt = (np + BM - 1) / BM;
    const int ntiles = nvt + npt;

    // A mapping: 64 rows x 64 k fp32 = 1024 float4 per chunk; 4/thread
    const int arow = tid >> 2;                 // 0..63
    const int akq  = (tid & 3) * 16;           // fp32 k offset within chunk
    const uint32_t aDst = (uint32_t)arow * ROWB + (uint32_t)akq * 2;

    // B mapping: 32 KB per chunk = 2048 x 16B; 8/thread
    uint32_t bSrcOff[8], bDstOff[8];
    #pragma unroll
    for (int i = 0; i < 8; i++) {
        int idx = tid + i * NT;                // 0..2047
        int row = idx >> 3;                    // 0..255
        int c16 = idx & 7;
        bSrcOff[i] = (uint32_t)row * 128u + (uint32_t)c16 * 16u;
        bDstOff[i] = (uint32_t)row * ROWB + (uint32_t)c16 * 16u;
    }

    const uint32_t aLdOff = (uint32_t)(((lane >> 3) & 1) * 8 + (lane & 7)) * ROWB + (uint32_t)(lane >> 4) * 16;
    const uint32_t bLdOff = (uint32_t)(((lane >> 4) & 1) * 8 + (lane & 7)) * ROWB + (uint32_t)((lane >> 3) & 1) * 16;

    // pack 8 fp32 -> uint4 of fp16
    auto packA = [](float4 f0, float4 f1) {
        uint4 hv;
        hv.x = (uint32_t)__half_as_ushort(__float2half_rn(f0.x)) |
               ((uint32_t)__half_as_ushort(__float2half_rn(f0.y)) << 16);
        hv.y = (uint32_t)__half_as_ushort(__float2half_rn(f0.z)) |
               ((uint32_t)__half_as_ushort(__float2half_rn(f0.w)) << 16);
        hv.z = (uint32_t)__half_as_ushort(__float2half_rn(f1.x)) |
               ((uint32_t)__half_as_ushort(__float2half_rn(f1.y)) << 16);
        hv.w = (uint32_t)__half_as_ushort(__float2half_rn(f1.z)) |
               ((uint32_t)__half_as_ushort(__float2half_rn(f1.w)) << 16);
        return hv;
    };

    for (;;) {
        __syncthreads();      // previous tile's smem fully consumed
        if (tid == 0) *sTile = atomicAdd(&g_ticket, 1);
        __syncthreads();
        const int tile = *sTile;
        if (tile >= ntiles) break;

        const int head  = (tile >= nvt);
        const int tIdx  = head ? (tile - nvt) : tile;
        const int count = head ? np : nv;
        const int base  = tIdx * BM;
        const int* list  = head ? g_pidx : g_vidx;
        const float* W2p = head ? pW2 : vW2;
        const float* B1p = head ? pB1 : vB1;
        const float* B2p = head ? pB2 : vB2;
        const int odim   = head ? 2 : 6;
        const unsigned char* wsrc = g_wpack + (size_t)head * (NCHUNK * 32768);

        // ---- tile prologue ----
        if (tid < BM) {
            int m = base + tid;
            sTok[tid] = (m < count) ? list[m] : list[0];
        }
        for (int i = tid; i < 6 * HDIM; i += NT) sW2[i] = (i < odim * HDIM) ? W2p[i] : 0.0f;
        if (tid < HDIM) sB1[tid] = B1p[tid];
        if (tid < odim) sB2[tid] = B2p[tid];
        __syncthreads();

        const float* aSrc = repr3 + (size_t)sTok[arow] * DIN + akq;

        float c[2][8][4];
        #pragma unroll
        for (int mi = 0; mi < 2; mi++)
            #pragma unroll
            for (int ni = 0; ni < 8; ni++)
                #pragma unroll
                for (int j = 0; j < 4; j++) c[mi][ni][j] = 0.0f;

        // ---- chunk 0 loads ----
        {
            #pragma unroll
            for (int i = 0; i < 8; i++)
                cp_async16(sb + B_OFF + bDstOff[i], wsrc + bSrcOff[i]);
            CP_COMMIT();
            float4 f0 = *(const float4*)(aSrc);
            float4 f1 = *(const float4*)(aSrc + 4);
            float4 f2 = *(const float4*)(aSrc + 8);
            float4 f3 = *(const float4*)(aSrc + 12);
            unsigned char* aP = smem + A_OFF;
            *(uint4*)(aP + aDst)      = packA(f0, f1);
            *(uint4*)(aP + aDst + 16) = packA(f2, f3);
            CP_WAIT0();
            __syncthreads();
        }

        // ---- main K loop: 8 chunks, one sync each ----
        for (int ch = 0; ch < NCHUNK; ch++) {
            const int s  = ch & 1;
            const int ns = s ^ 1;
            const bool more = (ch + 1 < NCHUNK);
            float4 f0, f1, f2, f3;
            if (more) {
                #pragma unroll
                for (int i = 0; i < 8; i++)
                    cp_async16(sb + B_OFF + ns * B_STAGE + bDstOff[i],
                               wsrc + (size_t)(ch + 1) * 32768 + bSrcOff[i]);
                CP_COMMIT();
                const float* ap = aSrc + (ch + 1) * KC;
                f0 = *(const float4*)(ap);
                f1 = *(const float4*)(ap + 4);
                f2 = *(const float4*)(ap + 8);
                f3 = *(const float4*)(ap + 12);
            }

            // 1024-cycle MMA region on stage s
            const uint32_t aB = sb + A_OFF + s * A_STAGE;
            const uint32_t bB = sb + B_OFF + s * B_STAGE;
            #pragma unroll
            for (int ks = 0; ks < 4; ks++) {
                uint32_t ah[2][4];
                #pragma unroll
                for (int mi = 0; mi < 2; mi++) {
                    uint32_t off = (uint32_t)(m0 + mi * 16) * ROWB + (uint32_t)ks * 32 + aLdOff;
                    ldm4(ah[mi], aB + off);
                }
                #pragma unroll
                for (int npp = 0; npp < 4; npp++) {
                    uint32_t off = (uint32_t)(n0 + npp * 16) * ROWB + (uint32_t)ks * 32 + bLdOff;
                    uint32_t b[4];
                    ldm4(b, bB + off);
                    #pragma unroll
                    for (int mi = 0; mi < 2; mi++) {
                        mma16816(c[mi][2 * npp],     ah[mi], b[0], b[1]);
                        mma16816(c[mi][2 * npp + 1], ah[mi], b[2], b[3]);
                    }
                }
            }

            if (more) {
                unsigned char* aP = smem + A_OFF + ns * A_STAGE;
                *(uint4*)(aP + aDst)      = packA(f0, f1);
                *(uint4*)(aP + aDst + 16) = packA(f2, f3);
                CP_WAIT0();
            }
            __syncthreads();
        }

        // ---- epilogue: bias + exact GELU + 256->{6,2} layer ----
        #pragma unroll
        for (int mi = 0; mi < 2; mi++) {
            #pragma unroll
            for (int half = 0; half < 2; half++) {
                float a6[6] = {0.f, 0.f, 0.f, 0.f, 0.f, 0.f};
                #pragma unroll
                for (int ni = 0; ni < 8; ni++) {
                    #pragma unroll
                    for (int e = 0; e < 2; e++) {
                        int col = n0 + ni * 8 + (lane & 3) * 2 + e;
                        float x = c[mi][ni][half * 2 + e] + sB1[col];
                        float hgl = 0.5f * x * (1.0f + erff(x * 0.70710678118654752f));
                        #pragma unroll
                        for (int o = 0; o < 6; o++)
                            a6[o] = fmaf(hgl, sW2[o * HDIM + col], a6[o]);
                    }
                }
                #pragma unroll
                for (int o = 0; o < 6; o++) {
                    a6[o] += __shfl_xor_sync(0xffffffffu, a6[o], 1);
                    a6[o] += __shfl_xor_sync(0xffffffffu, a6[o], 2);
                }
                if ((lane & 3) == 0) {
                    int row = m0 + mi * 16 + half * 8 + (lane >> 2);
                    #pragma unroll
                    for (int o = 0; o < 6; o++)
                        sRed[(wn * BM + row) * 6 + o] = a6[o];
                }
            }
        }
        __syncthreads();

        if (tid < BM && base + tid < count) {
            float* orow = out + (size_t)sTok[tid] * 6;
            #pragma unroll
            for (int o = 0; o < 6; o++) {
                if (o < odim) {
                    float v = sRed[(0 * BM + tid) * 6 + o] + sRed[(1 * BM + tid) * 6 + o]
                            + sRed[(2 * BM + tid) * 6 + o] + sRed[(3 * BM + tid) * 6 + o]
                            + sB2[o];
                    orow[o] = v;
                }
            }
        }
    }
}

// ---------------- launch ----------------
extern "C" void kernel_launch(void* const* d_in, const int* in_sizes, int n_in,
                              void* d_out, int out_size) {
    const float* repr3 = (const float*)d_in[0];
    const int*   ids   = (const int*)d_in[1];
    const float* vW1 = (const float*)d_in[2];
    const float* vb1 = (const float*)d_in[3];
    const float* vW2 = (const float*)d_in[4];
    const float* vb2 = (const float*)d_in[5];
    const float* pW1 = (const float*)d_in[6];
    const float* pb1 = (const float*)d_in[7];
    const float* pW2 = (const float*)d_in[8];
    const float* pb2 = (const float*)d_in[9];
    float* out = (float*)d_out;

    int mask_mode = 0;
    if (out_size >= TOKENS * 6 + 2 * TOKENS)      mask_mode = 1;
    else if (out_size >= TOKENS * 6 + TOKENS / 2) mask_mode = 2;

    cudaFuncSetAttribute(mlp_kernel, cudaFuncAttributeMaxDynamicSharedMemorySize, SMEM_TOTAL);

    pack_kernel<<<dim3(128, 2), 256>>>(vW1, pW1);
    classify_kernel<<<TOKENS / 256, 256>>>(ids, out, mask_mode);
    mlp_kernel<<<GRID, NT, SMEM_TOTAL>>>(repr3, vW2, vb1, vb2, pW2, pb1, pb2, out);
}

// round 7
// speedup vs baseline: 1.2754x; 1.2754x over previous
#include <cuda_runtime.h>
#include <cuda_fp16.h>
#include <math.h>
#include <stdint.h>

#define TOKENS 65536
#define DIN 512
#define HDIM 256
#define BM 64             // tokens per CTA tile
#define KC 32             // fp32 K elements per chunk
#define NCHUNK 16         // 512/32
#define NT 256            // threads per CTA
#define ROWB 80           // padded smem row bytes (32 fp16 = 64B + 16B pad)
#define GRID 304          // 2 CTAs/SM x 152 SMs, persistent

// ---- dynamic SMEM layout (bytes) ----
#define A_OFF     0       // 2 stages x 5120 (64 rows * 80, single fp16)
#define A_STAGE   5120
#define B_OFF     10240   // 2 stages x 20480 (256 rows * 80, single fp16)
#define B_STAGE   20480
#define TOK_OFF   51200   // int[64]
#define W2_OFF    51456   // float[6*256]
#define B1_OFF    57600   // float[256]
#define B2_OFF    58624   // float[8]
#define RED_OFF   58656   // float[4][64][6]
#define TILE_OFF  64800   // int
#define SMEM_TOTAL 64832

// ---------------- device globals (allocation-free scratch) ----------------
__device__ int g_vcount, g_pcount, g_ticket;
__device__ int g_vidx[TOKENS];
__device__ int g_pidx[TOKENS];
// prepacked W1 fp16, both heads: [head][chunk][256 rows x 64B]
__device__ __align__(16) unsigned char g_wpack[2 * NCHUNK * 16384];

// ---------------- PTX helpers ----------------
__device__ __forceinline__ uint32_t smem_u32(const void* p) {
    uint32_t a;
    asm("{ .reg .u64 t; cvta.to.shared.u64 t, %1; cvt.u32.u64 %0, t; }" : "=r"(a) : "l"(p));
    return a;
}
__device__ __forceinline__ void cp_async16(uint32_t dst, const void* src) {
    asm volatile("cp.async.ca.shared.global [%0], [%1], 16;" :: "r"(dst), "l"(src) : "memory");
}
#define CP_COMMIT() asm volatile("cp.async.commit_group;" ::: "memory")
#define CP_WAIT0()  asm volatile("cp.async.wait_group 0;" ::: "memory")

__device__ __forceinline__ void ldm4(uint32_t (&r)[4], uint32_t addr) {
    asm volatile("ldmatrix.sync.aligned.m8n8.x4.shared.b16 {%0,%1,%2,%3}, [%4];"
        : "=r"(r[0]), "=r"(r[1]), "=r"(r[2]), "=r"(r[3]) : "r"(addr));
}
__device__ __forceinline__ void mma16816(float (&d)[4], const uint32_t (&a)[4],
                                         uint32_t b0, uint32_t b1) {
    asm volatile(
        "mma.sync.aligned.m16n8k16.row.col.f32.f16.f16.f32 "
        "{%0,%1,%2,%3},{%4,%5,%6,%7},{%8,%9},{%0,%1,%2,%3};"
        : "+f"(d[0]), "+f"(d[1]), "+f"(d[2]), "+f"(d[3])
        : "r"(a[0]), "r"(a[1]), "r"(a[2]), "r"(a[3]), "r"(b0), "r"(b1));
}

// ---------------- kernel: prepack W1 fp16 + reset counters ----------------
__global__ void pack_kernel(const float* __restrict__ vW1, const float* __restrict__ pW1) {
    if (blockIdx.x == 0 && blockIdx.y == 0 && threadIdx.x == 0) {
        g_vcount = 0; g_pcount = 0; g_ticket = 0;
    }
    int head = blockIdx.y;
    const float* W = head ? pW1 : vW1;
    int q  = blockIdx.x * blockDim.x + threadIdx.x;  // 0..32767
    int n  = q >> 7;                                 // H row 0..255
    int kq = (q & 127) * 4;                          // k 0..508
    float4 f = *(const float4*)(W + (size_t)n * DIN + kq);

    uint16_t h0 = __half_as_ushort(__float2half_rn(f.x));
    uint16_t h1 = __half_as_ushort(__float2half_rn(f.y));
    uint16_t h2 = __half_as_ushort(__float2half_rn(f.z));
    uint16_t h3 = __half_as_ushort(__float2half_rn(f.w));
    uint2 hv;
    hv.x = (uint32_t)h0 | ((uint32_t)h1 << 16);
    hv.y = (uint32_t)h2 | ((uint32_t)h3 << 16);

    int chunk = kq >> 5;           // KC=32
    int kk = kq & 31;
    unsigned char* basep = g_wpack + (size_t)head * (NCHUNK * 16384) + (size_t)chunk * 16384;
    *(uint2*)(basep + (size_t)n * 64 + kk * 2) = hv;
}

// ---------------- kernel: classify + zero output + masks ----------------
__global__ void classify_kernel(const int* __restrict__ ids32,
                                float* __restrict__ out, int mask_mode) {
    __shared__ int sIs64;
    if (threadIdx.x < 32) {
        int v = ids32[2 * threadIdx.x + 1] | ids32[2 * threadIdx.x + 65] |
                ids32[2 * threadIdx.x + 129] | ids32[2 * threadIdx.x + 193];
        unsigned nz = __ballot_sync(0xffffffffu, v != 0);
        if (threadIdx.x == 0) sIs64 = (nz == 0);
    }
    __syncthreads();
    int t = blockIdx.x * blockDim.x + threadIdx.x;
    if (t >= TOKENS) return;
    int type = sIs64 ? ids32[2 * t] : ids32[t];
    bool vm = (type == 1);
    bool pm = (type == 2);

    float* row = out + (size_t)t * 6;
    #pragma unroll
    for (int o = 0; o < 6; o++) row[o] = 0.0f;

    if (mask_mode == 1) {
        out[TOKENS * 6 + t]          = vm ? 1.0f : 0.0f;
        out[TOKENS * 6 + TOKENS + t] = pm ? 1.0f : 0.0f;
    } else if (mask_mode == 2) {
        unsigned char* m = (unsigned char*)(out + TOKENS * 6);
        m[t]          = vm ? 1 : 0;
        m[TOKENS + t] = pm ? 1 : 0;
    }

    int lane = threadIdx.x & 31;
    unsigned vb = __ballot_sync(0xffffffffu, vm);
    if (vm) {
        int leader = __ffs(vb) - 1;
        int base = 0;
        if (lane == leader) base = atomicAdd(&g_vcount, __popc(vb));
        base = __shfl_sync(vb, base, leader);
        g_vidx[base + __popc(vb & ((1u << lane) - 1u))] = t;
    }
    unsigned pb = __ballot_sync(0xffffffffu, pm);
    if (pm) {
        int leader = __ffs(pb) - 1;
        int base = 0;
        if (lane == leader) base = atomicAdd(&g_pcount, __popc(pb));
        base = __shfl_sync(pb, base, leader);
        g_pidx[base + __popc(pb & ((1u << lane) - 1u))] = t;
    }
}

// ---------------- kernel: persistent single-fp16 HMMA MLP ----------------
__global__ __launch_bounds__(NT, 2)
void mlp_kernel(const float* __restrict__ repr3,
                const float* __restrict__ vW2, const float* __restrict__ vB1, const float* __restrict__ vB2,
                const float* __restrict__ pW2, const float* __restrict__ pB1, const float* __restrict__ pB2,
                float* __restrict__ out)
{
    extern __shared__ unsigned char smem[];
    const uint32_t sb = smem_u32(smem);
    const int tid  = threadIdx.x;
    const int wid  = tid >> 5;
    const int lane = tid & 31;
    const int wm = wid & 1;          // 2 M tiles of 32 rows
    const int wn = wid >> 1;         // 4 N tiles of 64 cols
    const int m0 = wm * 32;
    const int n0 = wn * 64;

    int*   sTok  = (int*)(smem + TOK_OFF);
    float* sW2   = (float*)(smem + W2_OFF);
    float* sB1   = (float*)(smem + B1_OFF);
    float* sB2   = (float*)(smem + B2_OFF);
    float* sRed  = (float*)(smem + RED_OFF);
    int*   sTile = (int*)(smem + TILE_OFF);

    const int nv = g_vcount, np = g_pcount;
    const int nvt = (nv + BM - 1) / BM;
    const int npt = (np + BM - 1) / BM;
    const int ntiles = nvt + npt;

    // per-thread constant mappings
    const int arow = tid >> 2;                 // 0..63
    const int akq  = (tid & 3) * 8;            // fp32 k offset within chunk
    const uint32_t aDst = (uint32_t)arow * ROWB + (uint32_t)akq * 2;

    uint32_t bSrcOff[4], bDstOff[4];
    #pragma unroll
    for (int i = 0; i < 4; i++) {
        int idx = tid + i * NT;                // 0..1023
        int row = idx >> 2;
        int c16 = idx & 3;
        bSrcOff[i] = (uint32_t)row * 64u + (uint32_t)c16 * 16u;
        bDstOff[i] = (uint32_t)row * ROWB + (uint32_t)c16 * 16u;
    }

    const uint32_t aLdOff = (uint32_t)(((lane >> 3) & 1) * 8 + (lane & 7)) * ROWB + (uint32_t)(lane >> 4) * 16;
    const uint32_t bLdOff = (uint32_t)(((lane >> 4) & 1) * 8 + (lane & 7)) * ROWB + (uint32_t)((lane >> 3) & 1) * 16;

    auto storeA = [&](unsigned char* aP, float4 f0, float4 f1) {
        uint4 hv;
        hv.x = (uint32_t)__half_as_ushort(__float2half_rn(f0.x)) |
               ((uint32_t)__half_as_ushort(__float2half_rn(f0.y)) << 16);
        hv.y = (uint32_t)__half_as_ushort(__float2half_rn(f0.z)) |
               ((uint32_t)__half_as_ushort(__float2half_rn(f0.w)) << 16);
        hv.z = (uint32_t)__half_as_ushort(__float2half_rn(f1.x)) |
               ((uint32_t)__half_as_ushort(__float2half_rn(f1.y)) << 16);
        hv.w = (uint32_t)__half_as_ushort(__float2half_rn(f1.z)) |
               ((uint32_t)__half_as_ushort(__float2half_rn(f1.w)) << 16);
        *(uint4*)(aP + aDst) = hv;
    };

    // ---- first ticket + B chunk-0 prefetch ----
    if (tid == 0) *sTile = atomicAdd(&g_ticket, 1);
    __syncthreads();
    int tile = *sTile;
    if (tile < ntiles) {
        int h = (tile >= nvt);
        const unsigned char* ws = g_wpack + (size_t)h * (NCHUNK * 16384);
        #pragma unroll
        for (int i = 0; i < 4; i++)
            cp_async16(sb + B_OFF + bDstOff[i], ws + bSrcOff[i]);
        CP_COMMIT();
    }

    int prevHead = -1;

    while (tile < ntiles) {
        const int head  = (tile >= nvt);
        const int tIdx  = head ? (tile - nvt) : tile;
        const int count = head ? np : nv;
        const int base  = tIdx * BM;
        const int* list  = head ? g_pidx : g_vidx;
        const int odim   = head ? 2 : 6;
        const unsigned char* wsrc = g_wpack + (size_t)head * (NCHUNK * 16384);

        // ---- tile prologue (W2/B1/B2 only on head change) ----
        if (tid < BM) {
            int m = base + tid;
            sTok[tid] = (m < count) ? list[m] : list[0];
        }
        if (head != prevHead) {
            const float* W2p = head ? pW2 : vW2;
            const float* B1p = head ? pB1 : vB1;
            const float* B2p = head ? pB2 : vB2;
            for (int i = tid; i < 6 * HDIM; i += NT) sW2[i] = (i < odim * HDIM) ? W2p[i] : 0.0f;
            if (tid < HDIM) sB1[tid] = B1p[tid];
            if (tid < odim) sB2[tid] = B2p[tid];
        }
        prevHead = head;
        __syncthreads();

        const float* aSrc = repr3 + (size_t)sTok[arow] * DIN + akq;

        float c[2][8][4];
        #pragma unroll
        for (int mi = 0; mi < 2; mi++)
            #pragma unroll
            for (int ni = 0; ni < 8; ni++)
                #pragma unroll
                for (int j = 0; j < 4; j++) c[mi][ni][j] = 0.0f;

        // ---- chunk 0: B already in flight (prefetched); gather A ----
        {
            float4 f0 = *(const float4*)(aSrc);
            float4 f1 = *(const float4*)(aSrc + 4);
            storeA(smem + A_OFF, f0, f1);
            CP_WAIT0();
            __syncthreads();
        }

        // ---- main K loop ----
        for (int ch = 0; ch < NCHUNK; ch++) {
            const int s  = ch & 1;
            const int ns = s ^ 1;
            float4 f0, f1;
            const bool more = (ch + 1 < NCHUNK);
            if (more) {
                #pragma unroll
                for (int i = 0; i < 4; i++)
                    cp_async16(sb + B_OFF + ns * B_STAGE + bDstOff[i],
                               wsrc + (size_t)(ch + 1) * 16384 + bSrcOff[i]);
                CP_COMMIT();
                f0 = *(const float4*)(aSrc + (ch + 1) * KC);
                f1 = *(const float4*)(aSrc + (ch + 1) * KC + 4);
            }

            const uint32_t aB = sb + A_OFF + s * A_STAGE;
            const uint32_t bB = sb + B_OFF + s * B_STAGE;
            #pragma unroll
            for (int ks = 0; ks < 2; ks++) {
                uint32_t ah[2][4];
                #pragma unroll
                for (int mi = 0; mi < 2; mi++) {
                    uint32_t off = (uint32_t)(m0 + mi * 16) * ROWB + (uint32_t)ks * 32 + aLdOff;
                    ldm4(ah[mi], aB + off);
                }
                #pragma unroll
                for (int npp = 0; npp < 4; npp++) {
                    uint32_t off = (uint32_t)(n0 + npp * 16) * ROWB + (uint32_t)ks * 32 + bLdOff;
                    uint32_t b[4];
                    ldm4(b, bB + off);
                    #pragma unroll
                    for (int mi = 0; mi < 2; mi++) {
                        mma16816(c[mi][2 * npp],     ah[mi], b[0], b[1]);
                        mma16816(c[mi][2 * npp + 1], ah[mi], b[2], b[3]);
                    }
                }
            }

            if (more) {
                storeA(smem + A_OFF + ns * A_STAGE, f0, f1);
                CP_WAIT0();
            }
            __syncthreads();
        }

        // ---- grab next ticket + prefetch its B chunk-0 (stage 0 is free) ----
        if (tid == 0) *sTile = atomicAdd(&g_ticket, 1);
        __syncthreads();
        const int ntile = *sTile;
        if (ntile < ntiles) {
            int nh = (ntile >= nvt);
            const unsigned char* nws = g_wpack + (size_t)nh * (NCHUNK * 16384);
            #pragma unroll
            for (int i = 0; i < 4; i++)
                cp_async16(sb + B_OFF + bDstOff[i], nws + bSrcOff[i]);
            CP_COMMIT();
        }

        // ---- epilogue: bias + exact GELU + 256->{6,2} layer ----
        if (odim == 6) {
            #pragma unroll
            for (int mi = 0; mi < 2; mi++) {
                #pragma unroll
                for (int half = 0; half < 2; half++) {
                    float a6[6] = {0.f, 0.f, 0.f, 0.f, 0.f, 0.f};
                    #pragma unroll
                    for (int ni = 0; ni < 8; ni++) {
                        #pragma unroll
                        for (int e = 0; e < 2; e++) {
                            int col = n0 + ni * 8 + (lane & 3) * 2 + e;
                            float x = c[mi][ni][half * 2 + e] + sB1[col];
                            float hgl = 0.5f * x * (1.0f + erff(x * 0.70710678118654752f));
                            #pragma unroll
                            for (int o = 0; o < 6; o++)
                                a6[o] = fmaf(hgl, sW2[o * HDIM + col], a6[o]);
                        }
                    }
                    #pragma unroll
                    for (int o = 0; o < 6; o++) {
                        a6[o] += __shfl_xor_sync(0xffffffffu, a6[o], 1);
                        a6[o] += __shfl_xor_sync(0xffffffffu, a6[o], 2);
                    }
                    if ((lane & 3) == 0) {
                        int row = m0 + mi * 16 + half * 8 + (lane >> 2);
                        #pragma unroll
                        for (int o = 0; o < 6; o++)
                            sRed[(wn * BM + row) * 6 + o] = a6[o];
                    }
                }
            }
        } else {
            #pragma unroll
            for (int mi = 0; mi < 2; mi++) {
                #pragma unroll
                for (int half = 0; half < 2; half++) {
                    float a2[2] = {0.f, 0.f};
                    #pragma unroll
                    for (int ni = 0; ni < 8; ni++) {
                        #pragma unroll
                        for (int e = 0; e < 2; e++) {
                            int col = n0 + ni * 8 + (lane & 3) * 2 + e;
                            float x = c[mi][ni][half * 2 + e] + sB1[col];
                            float hgl = 0.5f * x * (1.0f + erff(x * 0.70710678118654752f));
                            a2[0] = fmaf(hgl, sW2[0 * HDIM + col], a2[0]);
                            a2[1] = fmaf(hgl, sW2[1 * HDIM + col], a2[1]);
                        }
                    }
                    #pragma unroll
                    for (int o = 0; o < 2; o++) {
                        a2[o] += __shfl_xor_sync(0xffffffffu, a2[o], 1);
                        a2[o] += __shfl_xor_sync(0xffffffffu, a2[o], 2);
                    }
                    if ((lane & 3) == 0) {
                        int row = m0 + mi * 16 + half * 8 + (lane >> 2);
                        sRed[(wn * BM + row) * 6 + 0] = a2[0];
                        sRed[(wn * BM + row) * 6 + 1] = a2[1];
                    }
                }
            }
        }
        __syncthreads();

        if (tid < BM && base + tid < count) {
            float* orow = out + (size_t)sTok[tid] * 6;
            #pragma unroll
            for (int o = 0; o < 6; o++) {
                if (o < odim) {
                    float v = sRed[(0 * BM + tid) * 6 + o] + sRed[(1 * BM + tid) * 6 + o]
                            + sRed[(2 * BM + tid) * 6 + o] + sRed[(3 * BM + tid) * 6 + o]
                            + sB2[o];
                    orow[o] = v;
                }
            }
        }
        __syncthreads();   // sTok/sRed consumed before next prologue overwrites
        tile = ntile;
    }
}

// ---------------- launch ----------------
extern "C" void kernel_launch(void* const* d_in, const int* in_sizes, int n_in,
                              void* d_out, int out_size) {
    const float* repr3 = (const float*)d_in[0];
    const int*   ids   = (const int*)d_in[1];
    const float* vW1 = (const float*)d_in[2];
    const float* vb1 = (const float*)d_in[3];
    const float* vW2 = (const float*)d_in[4];
    const float* vb2 = (const float*)d_in[5];
    const float* pW1 = (const float*)d_in[6];
    const float* pb1 = (const float*)d_in[7];
    const float* pW2 = (const float*)d_in[8];
    const float* pb2 = (const float*)d_in[9];
    float* out = (float*)d_out;

    int mask_mode = 0;
    if (out_size >= TOKENS * 6 + 2 * TOKENS)      mask_mode = 1;
    else if (out_size >= TOKENS * 6 + TOKENS / 2) mask_mode = 2;

    cudaFuncSetAttribute(mlp_kernel, cudaFuncAttributeMaxDynamicSharedMemorySize, SMEM_TOTAL);

    pack_kernel<<<dim3(128, 2), 256>>>(vW1, pW1);
    classify_kernel<<<TOKENS / 256, 256>>>(ids, out, mask_mode);
    mlp_kernel<<<GRID, NT, SMEM_TOTAL>>>(repr3, vW2, vb1, vb2, pW2, pb1, pb2, out);
}